// round 1
// baseline (speedup 1.0000x reference)
#include <cuda_runtime.h>
#include <cstdint>
#include <math.h>

#define L      65536
#define IMG    256
#define BATCH  2
#define DIMC   128
#define HEADS  8
#define CH     16

// ---- scratch (device globals; no allocation allowed) ----
__device__ float g_qkv[(size_t)BATCH * 384 * L];   // pointwise qkv output
__device__ float g_v  [(size_t)BATCH * DIMC * L];  // depthwise v
__device__ float g_S  [BATCH * HEADS * CH * CH];   // q·k^T Gram
__device__ float g_nq [BATCH * HEADS * CH];        // sum q^2
__device__ float g_nk [BATCH * HEADS * CH];        // sum k^2
__device__ float g_M  [BATCH * DIMC * DIMC];       // proj @ blockdiag(attn)

// ------------------------------------------------------------------
__global__ void zero_acc() {
    int t = blockIdx.x * blockDim.x + threadIdx.x;
    if (t < BATCH * HEADS * CH * CH) g_S[t] = 0.f;
    if (t < BATCH * HEADS * CH) { g_nq[t] = 0.f; g_nk[t] = 0.f; }
}

// ------------------------------------------------------------------
// Generic GEMM with K=128: Y[z][o][p] = sum_k W[z][o][k] * X[z][k][p]
// grid: (L/128, OC/64, BATCH), block 256.
__global__ __launch_bounds__(256) void gemm_k128(
    const float* __restrict__ W, int wsb,
    const float* __restrict__ X, size_t xsb,
    float* __restrict__ Y, size_t ysb)
{
    const float* Wb = W + (size_t)blockIdx.z * wsb;
    const float* Xb = X + (size_t)blockIdx.z * xsb;
    float*       Yb = Y + (size_t)blockIdx.z * ysb;
    const int p0 = blockIdx.x * 128;
    const int o0 = blockIdx.y * 64;

    __shared__ float sW[16][64];
    __shared__ float sX[16][128];

    const int t  = threadIdx.x;
    const int tx = t & 31;
    const int ty = t >> 5;
    const int pp = tx * 4;

    float acc[8][4];
#pragma unroll
    for (int i = 0; i < 8; i++)
#pragma unroll
        for (int j = 0; j < 4; j++) acc[i][j] = 0.f;

    for (int k0 = 0; k0 < 128; k0 += 16) {
        // load W tile (64 o x 16 k), transposed into sW[k][o]
        {
            int o = t >> 2;            // t/4
            int k = (t & 3) * 4;
            float4 w4 = *(const float4*)(Wb + (size_t)(o0 + o) * 128 + k0 + k);
            sW[k + 0][o] = w4.x; sW[k + 1][o] = w4.y;
            sW[k + 2][o] = w4.z; sW[k + 3][o] = w4.w;
        }
        // load X tile (16 k x 128 p)
#pragma unroll
        for (int i = 0; i < 2; i++) {
            int f4  = t + i * 256;     // 0..511
            int r   = f4 >> 5;
            int cid = f4 & 31;
            *(float4*)&sX[r][cid * 4] =
                *(const float4*)(Xb + (size_t)(k0 + r) * L + p0 + cid * 4);
        }
        __syncthreads();

#pragma unroll
        for (int kk = 0; kk < 16; kk++) {
            float4 A0 = *(float4*)&sW[kk][ty * 8];
            float4 A1 = *(float4*)&sW[kk][ty * 8 + 4];
            float4 B4 = *(float4*)&sX[kk][pp];
            float av[8] = {A0.x, A0.y, A0.z, A0.w, A1.x, A1.y, A1.z, A1.w};
            float bv[4] = {B4.x, B4.y, B4.z, B4.w};
#pragma unroll
            for (int i = 0; i < 8; i++)
#pragma unroll
                for (int j = 0; j < 4; j++) acc[i][j] += av[i] * bv[j];
        }
        __syncthreads();
    }

#pragma unroll
    for (int i = 0; i < 8; i++) {
        float4 o4 = make_float4(acc[i][0], acc[i][1], acc[i][2], acc[i][3]);
        *(float4*)(Yb + (size_t)(o0 + ty * 8 + i) * L + p0 + pp) = o4;
    }
}

// ------------------------------------------------------------------
// Depthwise 3x3 on q & k channels of one head + Gram/norm reduction.
// grid: (IMG/32, IMG/8, BATCH*HEADS), block 256 (=32x8 pixel tile).
__global__ __launch_bounds__(256) void dw_qk_gram(const float* __restrict__ dww)
{
    __shared__ float s_in[32 * 340];   // 32 ch x 10 x 34 (halo tile)
    __shared__ float w_s[32 * 9];

    const int z = blockIdx.z;          // b*8 + h
    const int b = z >> 3, h = z & 7;
    const int x0 = blockIdx.x * 32, y0 = blockIdx.y * 8;
    const int t = threadIdx.x;

    // weights: q chans h*16.., k chans 128+h*16..
    for (int i = t; i < 32 * 9; i += 256) {
        int lc = i / 9, j = i % 9;
        int gch = (lc < 16) ? (h * 16 + lc) : (128 + h * 16 + (lc - 16));
        w_s[i] = dww[gch * 9 + j];
    }
    // halo tile load
    const float* srcq = g_qkv + ((size_t)b * 384 + h * 16) * L;
    const float* srck = g_qkv + ((size_t)b * 384 + 128 + h * 16) * L;
    for (int idx = t; idx < 32 * 340; idx += 256) {
        int lc = idx / 340, rem = idx % 340;
        int r = rem / 34, cc = rem % 34;
        int y = y0 + r - 1, x = x0 + cc - 1;
        float v = 0.f;
        if ((unsigned)y < IMG && (unsigned)x < IMG) {
            const float* src = (lc < 16) ? srcq : srck;
            int c = (lc < 16) ? lc : (lc - 16);
            v = src[(size_t)c * L + y * IMG + x];
        }
        s_in[idx] = v;
    }
    __syncthreads();

    const int tx = t & 31, ty = t >> 5;
    float q_r[16], k_r[16];
#pragma unroll
    for (int c = 0; c < 16; c++) {
        const float* bq = &s_in[c * 340 + ty * 34 + tx];
        const float* wq = &w_s[c * 9];
        const float* bk = &s_in[(16 + c) * 340 + ty * 34 + tx];
        const float* wk = &w_s[(16 + c) * 9];
        float aq = 0.f, ak = 0.f;
#pragma unroll
        for (int dy = 0; dy < 3; dy++)
#pragma unroll
            for (int dx = 0; dx < 3; dx++) {
                aq += wq[dy * 3 + dx] * bq[dy * 34 + dx];
                ak += wk[dy * 3 + dx] * bk[dy * 34 + dx];
            }
        q_r[c] = aq; k_r[c] = ak;
    }
    __syncthreads();   // all conv reads done before smem reuse

    // repurpose s_in: q_s[16][257] then k_s[16][257] (pitch 257 -> conflict-free)
    float* q_s = s_in;
    float* k_s = s_in + 16 * 257;
#pragma unroll
    for (int c = 0; c < 16; c++) {
        q_s[c * 257 + t] = q_r[c];
        k_s[c * 257 + t] = k_r[c];
    }
    __syncthreads();

    // Gram: thread t -> (c,d)
    {
        int c = t >> 4, d = t & 15;
        float s = 0.f;
        for (int p = 0; p < 256; p++)
            s += q_s[c * 257 + p] * k_s[d * 257 + p];
        atomicAdd(&g_S[(z * 16 + c) * 16 + d], s);
    }
    if (t < 16) {
        float s = 0.f;
        for (int p = 0; p < 256; p++) { float v = q_s[t * 257 + p]; s += v * v; }
        atomicAdd(&g_nq[z * 16 + t], s);
    } else if (t < 32) {
        int c = t - 16;
        float s = 0.f;
        for (int p = 0; p < 256; p++) { float v = k_s[c * 257 + p]; s += v * v; }
        atomicAdd(&g_nk[z * 16 + c], s);
    }
}

// ------------------------------------------------------------------
// Depthwise 3x3 on v channels of one head -> g_v.
// grid: (IMG/32, IMG/8, BATCH*HEADS), block 256.
__global__ __launch_bounds__(256) void dw_v(const float* __restrict__ dww)
{
    __shared__ float s_in[16 * 340];
    __shared__ float w_s[16 * 9];

    const int z = blockIdx.z;
    const int b = z >> 3, h = z & 7;
    const int x0 = blockIdx.x * 32, y0 = blockIdx.y * 8;
    const int t = threadIdx.x;

    for (int i = t; i < 16 * 9; i += 256)
        w_s[i] = dww[(256 + h * 16) * 9 + i];     // channels contiguous

    const float* src = g_qkv + ((size_t)b * 384 + 256 + h * 16) * L;
    for (int idx = t; idx < 16 * 340; idx += 256) {
        int lc = idx / 340, rem = idx % 340;
        int r = rem / 34, cc = rem % 34;
        int y = y0 + r - 1, x = x0 + cc - 1;
        float v = 0.f;
        if ((unsigned)y < IMG && (unsigned)x < IMG)
            v = src[(size_t)lc * L + y * IMG + x];
        s_in[idx] = v;
    }
    __syncthreads();

    const int tx = t & 31, ty = t >> 5;
    const int p = (y0 + ty) * IMG + x0 + tx;
    float* dst = g_v + ((size_t)b * DIMC + h * 16) * L;
#pragma unroll
    for (int lc = 0; lc < 16; lc++) {
        const float* base = &s_in[lc * 340 + ty * 34 + tx];
        const float* w = &w_s[lc * 9];
        float acc = 0.f;
#pragma unroll
        for (int dy = 0; dy < 3; dy++)
#pragma unroll
            for (int dx = 0; dx < 3; dx++)
                acc += w[dy * 3 + dx] * base[dy * 34 + dx];
        dst[(size_t)lc * L + p] = acc;
    }
}

// ------------------------------------------------------------------
// Tiny: attention matrices + M_b = proj_w @ blockdiag(attn_final).
// 1 block, 256 threads (one per (b,h,c) row).
__global__ void attn_small(const float* __restrict__ attca_w,
                           const float* __restrict__ proj_w,
                           const float* __restrict__ temperature)
{
    __shared__ float attnF[BATCH * HEADS * CH][CH];
    const int t = threadIdx.x;
    {
        int bh = t >> 4;
        int c  = t & 15;
        int h  = bh & 7;
        float dq = fmaxf(sqrtf(g_nq[bh * 16 + c]), 1e-12f);
        float temp = temperature[h];
        float row[16];
#pragma unroll
        for (int d = 0; d < 16; d++) {
            float dk = fmaxf(sqrtf(g_nk[bh * 16 + d]), 1e-12f);
            row[d] = g_S[(bh * 16 + c) * 16 + d] / (dq * dk) * temp;
        }
        float m = row[0];
#pragma unroll
        for (int d = 1; d < 16; d++) m = fmaxf(m, row[d]);
        float ex[16], sum = 0.f;
#pragma unroll
        for (int d = 0; d < 16; d++) { ex[d] = expf(row[d] - m); sum += ex[d]; }
        float inv = 1.f / sum;
        float a1[16];
#pragma unroll
        for (int d = 0; d < 16; d++) {
            float r = fmaxf(row[d], 0.f);
            float a = r * r;
            float g = a * 0.5f * (1.f + erff(a * 0.7071067811865476f));
            a1[d] = g * a;
        }
#pragma unroll
        for (int d = 0; d < 16; d++) {
            float sc = 0.f, sh = 0.f;
#pragma unroll
            for (int e = 0; e < 16; e++) {
                sc += attca_w[d * 16 + e] * a1[e];
                sh += attca_w[(16 + d) * 16 + e] * a1[e];
            }
            attnF[bh * 16 + c][d] = ex[d] * inv * (1.f + sc) + sh;
        }
    }
    __syncthreads();
    // M[b][o][h*16+d] = sum_c proj_w[o][h*16+c] * attnF[b,h,c][d]
    for (int i = 0; i < 128; i++) {
        int e  = t + (i << 8);           // 0..32767
        int b2 = e >> 14;
        int o  = (e >> 7) & 127;
        int j  = e & 127;
        int h2 = j >> 4, d = j & 15;
        float s = 0.f;
#pragma unroll
        for (int c2 = 0; c2 < 16; c2++)
            s += proj_w[o * 128 + h2 * 16 + c2] * attnF[(b2 * 8 + h2) * 16 + c2][d];
        g_M[e] = s;
    }
}

// ------------------------------------------------------------------
extern "C" void kernel_launch(void* const* d_in, const int* in_sizes, int n_in,
                              void* d_out, int out_size)
{
    const float* x           = (const float*)d_in[0];
    const float* qkv_w       = (const float*)d_in[1];
    const float* dw_w        = (const float*)d_in[2];
    const float* proj_w      = (const float*)d_in[3];
    const float* attca_w     = (const float*)d_in[4];
    const float* temperature = (const float*)d_in[5];
    float* out = (float*)d_out;

    float *p_qkv, *p_v, *p_M;
    cudaGetSymbolAddress((void**)&p_qkv, g_qkv);
    cudaGetSymbolAddress((void**)&p_v,   g_v);
    cudaGetSymbolAddress((void**)&p_M,   g_M);

    zero_acc<<<16, 256>>>();
    // qkv pointwise: [384x128] @ x[b][128][L]
    gemm_k128<<<dim3(L / 128, 384 / 64, BATCH), 256>>>(
        qkv_w, 0, x, (size_t)DIMC * L, p_qkv, (size_t)384 * L);
    // depthwise q/k + Gram reductions
    dw_qk_gram<<<dim3(IMG / 32, IMG / 8, BATCH * HEADS), 256>>>(dw_w);
    // depthwise v
    dw_v<<<dim3(IMG / 32, IMG / 8, BATCH * HEADS), 256>>>(dw_w);
    // attention + fold proj into M
    attn_small<<<1, 256>>>(attca_w, proj_w, temperature);
    // out = M_b @ v
    gemm_k128<<<dim3(L / 128, DIMC / 64, BATCH), 256>>>(
        p_M, DIMC * DIMC, p_v, (size_t)DIMC * L, out, (size_t)DIMC * L);
}

// round 5
// speedup vs baseline: 1.1835x; 1.1835x over previous
#include <cuda_runtime.h>
#include <cuda_bf16.h>
#include <cstdint>
#include <math.h>

#define L      65536
#define IMG    256
#define BATCH  2
#define DIMC   128
#define HEADS  8
#define CH     16

// ---- scratch (device globals; no allocation allowed) ----
__device__ float g_qkv[(size_t)BATCH * 384 * L];   // pointwise qkv output
__device__ float g_v  [(size_t)BATCH * DIMC * L];  // depthwise v
__device__ float g_S  [BATCH * HEADS * CH * CH];   // q·k^T Gram
__device__ float g_nq [BATCH * HEADS * CH];        // sum q^2
__device__ float g_nk [BATCH * HEADS * CH];        // sum k^2
__device__ float g_M  [BATCH * DIMC * DIMC];       // proj @ blockdiag(attn)

// ================= mma.sync helpers (sm_80+ PTX, valid on compute_103) ======
__device__ __forceinline__ uint32_t smem_u32(const void* p) {
    uint32_t a;
    asm("{ .reg .u64 t; cvta.to.shared.u64 t, %1; cvt.u32.u64 %0, t; }"
        : "=r"(a) : "l"(p));
    return a;
}
__device__ __forceinline__ void ldsm_x4(uint32_t* r, uint32_t addr) {
    asm volatile("ldmatrix.sync.aligned.m8n8.x4.shared.b16 {%0,%1,%2,%3}, [%4];"
                 : "=r"(r[0]), "=r"(r[1]), "=r"(r[2]), "=r"(r[3]) : "r"(addr));
}
__device__ __forceinline__ void ldsm_x4_t(uint32_t* r, uint32_t addr) {
    asm volatile("ldmatrix.sync.aligned.m8n8.x4.trans.shared.b16 {%0,%1,%2,%3}, [%4];"
                 : "=r"(r[0]), "=r"(r[1]), "=r"(r[2]), "=r"(r[3]) : "r"(addr));
}
__device__ __forceinline__ void mma_bf16(float* c, const uint32_t* a,
                                         uint32_t b0, uint32_t b1) {
    asm volatile(
        "mma.sync.aligned.m16n8k16.row.col.f32.bf16.bf16.f32 "
        "{%0,%1,%2,%3}, {%4,%5,%6,%7}, {%8,%9}, {%0,%1,%2,%3};"
        : "+f"(c[0]), "+f"(c[1]), "+f"(c[2]), "+f"(c[3])
        : "r"(a[0]), "r"(a[1]), "r"(a[2]), "r"(a[3]), "r"(b0), "r"(b1));
}

// fp32 -> bf16 hi/lo split, packed pairs (first elem low 16 bits)
__device__ __forceinline__ void split_pack(float a, float b,
                                           uint32_t& hi, uint32_t& lo) {
    __nv_bfloat16 ha = __float2bfloat16(a);
    __nv_bfloat16 hb = __float2bfloat16(b);
    float ra = a - __bfloat162float(ha);
    float rb = b - __bfloat162float(hb);
    __nv_bfloat16 la = __float2bfloat16(ra);
    __nv_bfloat16 lb = __float2bfloat16(rb);
    hi = (uint32_t)__bfloat16_as_ushort(ha) | ((uint32_t)__bfloat16_as_ushort(hb) << 16);
    lo = (uint32_t)__bfloat16_as_ushort(la) | ((uint32_t)__bfloat16_as_ushort(lb) << 16);
}

// smem layout (bf16 elements), pitch 136 => row stride 272B => 4-bank shift
// per row => conflict-free ldmatrix for both A (non-trans) and B (trans).
#define PITCH     136
#define A_ELEMS   (128 * PITCH)
#define OFF_A_HI  0
#define OFF_A_LO  A_ELEMS
#define OFF_B_HI  (2 * A_ELEMS)
#define OFF_B_LO  (3 * A_ELEMS)
#define SM_BYTES  (4 * A_ELEMS * 2)   // 139264

// ------------------------------------------------------------------
// Tensor-core GEMM (bf16 3-split via mma.sync):
//   Y[z][o0..o0+127][p0..p0+127] = sum_k A[z][o][k] * X[z][k][p]
// grid: (L/128, OC/128, BATCH), block 256, dyn smem SM_BYTES.
__global__ __launch_bounds__(256) void tc_gemm(
    const float* __restrict__ A, size_t a_bs,
    const float* __restrict__ X, size_t x_bs,
    float* __restrict__ Y, size_t y_bs)
{
    extern __shared__ __nv_bfloat16 smem[];
    const uint32_t sb = smem_u32(smem);

    const int t = threadIdx.x;
    const int bz = blockIdx.z;
    const int o0 = blockIdx.y * 128;
    const int p0 = blockIdx.x * 128;

    const float* Ab = A + (size_t)bz * a_bs;
    const float* Xb = X + (size_t)bz * x_bs;
    float*       Yb = Y + (size_t)bz * y_bs;

    // ---- A tile: 128 o x 128 k, f32 -> bf16 hi/lo, [o][k] pitch 136 ----
    {
        const int o = t >> 1;
        const int kh = (t & 1) * 64;
        const float* ag = Ab + (size_t)(o0 + o) * 128 + kh;
        uint32_t* dh = (uint32_t*)(smem + OFF_A_HI + o * PITCH + kh);
        uint32_t* dl = (uint32_t*)(smem + OFF_A_LO + o * PITCH + kh);
#pragma unroll
        for (int i = 0; i < 16; i++) {
            float4 v = *(const float4*)(ag + i * 4);
            uint32_t h0, l0, h1, l1;
            split_pack(v.x, v.y, h0, l0);
            split_pack(v.z, v.w, h1, l1);
            dh[i * 2 + 0] = h0; dh[i * 2 + 1] = h1;
            dl[i * 2 + 0] = l0; dl[i * 2 + 1] = l1;
        }
    }
    // ---- B tile: 128 k x 128 p, f32 -> bf16 hi/lo, [k][p] pitch 136 ----
    {
        const int pq = t & 63;          // p pair: p = 2*pq
        const int ks = (t >> 6) * 32;   // 32 k rows per thread group
        const float* xg = Xb + p0 + pq * 2;
#pragma unroll
        for (int kk = 0; kk < 32; kk++) {
            const int k = ks + kk;
            float2 v = *(const float2*)(xg + (size_t)k * L);
            uint32_t hi, lo;
            split_pack(v.x, v.y, hi, lo);
            ((uint32_t*)(smem + OFF_B_HI + k * PITCH))[pq] = hi;
            ((uint32_t*)(smem + OFF_B_LO + k * PITCH))[pq] = lo;
        }
    }
    __syncthreads();

    // ---- warp tiling: 8 warps = 2(o) x 4(p); warp tile 64o x 32p ----
    const int lane = t & 31, wid = t >> 5;
    const int wo = wid >> 2, wp = wid & 3;
    const int lr = lane & 7, sel = lane >> 3;

    // ldmatrix lane addresses (element offsets)
    const uint32_t aoff = (uint32_t)(wo * 64 + (sel & 1) * 8 + lr) * PITCH +
                          (sel >> 1) * 8;
    const uint32_t boff = (uint32_t)((sel & 1) * 8 + lr) * PITCH +
                          wp * 32 + (sel >> 1) * 8;

    const uint32_t aBase[2] = { sb + OFF_A_HI * 2, sb + OFF_A_LO * 2 };
    const uint32_t bBase[2] = { sb + OFF_B_HI * 2, sb + OFF_B_LO * 2 };

    float acc[4][4][4];
#pragma unroll
    for (int mi = 0; mi < 4; mi++)
#pragma unroll
        for (int ni = 0; ni < 4; ni++)
#pragma unroll
            for (int j = 0; j < 4; j++) acc[mi][ni][j] = 0.f;

    uint32_t afr[4][4];
    // products: s=0: Ahi*Bhi, s=1: Ahi*Blo (A frags reused), s=2: Alo*Bhi
#pragma unroll
    for (int s = 0; s < 3; s++) {
        const uint32_t ab = aBase[s == 2 ? 1 : 0];
        const uint32_t bb = bBase[s == 1 ? 1 : 0];
#pragma unroll
        for (int k0 = 0; k0 < 128; k0 += 16) {
            if (s != 1) {
                const uint32_t al = ab + (aoff + k0) * 2;
#pragma unroll
                for (int mi = 0; mi < 4; mi++)
                    ldsm_x4(afr[mi], al + mi * 16 * PITCH * 2);
            } else {
                // reuse A-hi frags loaded in s==0 only if k order matches;
                // simplest correct: reload (kept cheap, conflict-free)
                const uint32_t al = ab + (aoff + k0) * 2;
#pragma unroll
                for (int mi = 0; mi < 4; mi++)
                    ldsm_x4(afr[mi], al + mi * 16 * PITCH * 2);
            }
            uint32_t bfr[2][4];
            const uint32_t bl = bb + (boff + (uint32_t)k0 * PITCH) * 2;
            ldsm_x4_t(bfr[0], bl);
            ldsm_x4_t(bfr[1], bl + 16 * 2);
#pragma unroll
            for (int mi = 0; mi < 4; mi++) {
                mma_bf16(acc[mi][0], afr[mi], bfr[0][0], bfr[0][1]);
                mma_bf16(acc[mi][1], afr[mi], bfr[0][2], bfr[0][3]);
                mma_bf16(acc[mi][2], afr[mi], bfr[1][0], bfr[1][1]);
                mma_bf16(acc[mi][3], afr[mi], bfr[1][2], bfr[1][3]);
            }
        }
    }

    // ---- epilogue: write D (f32) ----
    const int gID = lane >> 2, q4 = lane & 3;
#pragma unroll
    for (int mi = 0; mi < 4; mi++) {
        const int o = o0 + wo * 64 + mi * 16 + gID;
#pragma unroll
        for (int ni = 0; ni < 4; ni++) {
            const int p = p0 + wp * 32 + ni * 8 + q4 * 2;
            *(float2*)(Yb + (size_t)o * L + p) =
                make_float2(acc[mi][ni][0], acc[mi][ni][1]);
            *(float2*)(Yb + (size_t)(o + 8) * L + p) =
                make_float2(acc[mi][ni][2], acc[mi][ni][3]);
        }
    }
}

// ------------------------------------------------------------------
__global__ void zero_acc() {
    int t = blockIdx.x * blockDim.x + threadIdx.x;
    if (t < BATCH * HEADS * CH * CH) g_S[t] = 0.f;
    if (t < BATCH * HEADS * CH) { g_nq[t] = 0.f; g_nk[t] = 0.f; }
}

// ------------------------------------------------------------------
// Depthwise 3x3 on q & k channels of one head + Gram/norm reduction.
__global__ __launch_bounds__(256) void dw_qk_gram(const float* __restrict__ dww)
{
    __shared__ float s_in[32 * 340];
    __shared__ float w_s[32 * 9];

    const int z = blockIdx.z;
    const int b = z >> 3, h = z & 7;
    const int x0 = blockIdx.x * 32, y0 = blockIdx.y * 8;
    const int t = threadIdx.x;

    for (int i = t; i < 32 * 9; i += 256) {
        int lc = i / 9, j = i % 9;
        int gch = (lc < 16) ? (h * 16 + lc) : (128 + h * 16 + (lc - 16));
        w_s[i] = dww[gch * 9 + j];
    }
    const float* srcq = g_qkv + ((size_t)b * 384 + h * 16) * L;
    const float* srck = g_qkv + ((size_t)b * 384 + 128 + h * 16) * L;
    for (int idx = t; idx < 32 * 340; idx += 256) {
        int lc = idx / 340, rem = idx % 340;
        int r = rem / 34, cc = rem % 34;
        int y = y0 + r - 1, x = x0 + cc - 1;
        float v = 0.f;
        if ((unsigned)y < IMG && (unsigned)x < IMG) {
            const float* src = (lc < 16) ? srcq : srck;
            int c = (lc < 16) ? lc : (lc - 16);
            v = src[(size_t)c * L + y * IMG + x];
        }
        s_in[idx] = v;
    }
    __syncthreads();

    const int tx = t & 31, ty = t >> 5;
    float q_r[16], k_r[16];
#pragma unroll
    for (int c = 0; c < 16; c++) {
        const float* bq = &s_in[c * 340 + ty * 34 + tx];
        const float* wq = &w_s[c * 9];
        const float* bk = &s_in[(16 + c) * 340 + ty * 34 + tx];
        const float* wk = &w_s[(16 + c) * 9];
        float aq = 0.f, ak = 0.f;
#pragma unroll
        for (int dy = 0; dy < 3; dy++)
#pragma unroll
            for (int dx = 0; dx < 3; dx++) {
                aq += wq[dy * 3 + dx] * bq[dy * 34 + dx];
                ak += wk[dy * 3 + dx] * bk[dy * 34 + dx];
            }
        q_r[c] = aq; k_r[c] = ak;
    }
    __syncthreads();

    float* q_s = s_in;
    float* k_s = s_in + 16 * 257;
#pragma unroll
    for (int c = 0; c < 16; c++) {
        q_s[c * 257 + t] = q_r[c];
        k_s[c * 257 + t] = k_r[c];
    }
    __syncthreads();

    {
        int c = t >> 4, d = t & 15;
        float s = 0.f;
        for (int p = 0; p < 256; p++)
            s += q_s[c * 257 + p] * k_s[d * 257 + p];
        atomicAdd(&g_S[(z * 16 + c) * 16 + d], s);
    }
    if (t < 16) {
        float s = 0.f;
        for (int p = 0; p < 256; p++) { float v = q_s[t * 257 + p]; s += v * v; }
        atomicAdd(&g_nq[z * 16 + t], s);
    } else if (t < 32) {
        int c = t - 16;
        float s = 0.f;
        for (int p = 0; p < 256; p++) { float v = k_s[c * 257 + p]; s += v * v; }
        atomicAdd(&g_nk[z * 16 + c], s);
    }
}

// ------------------------------------------------------------------
__global__ __launch_bounds__(256) void dw_v(const float* __restrict__ dww)
{
    __shared__ float s_in[16 * 340];
    __shared__ float w_s[16 * 9];

    const int z = blockIdx.z;
    const int b = z >> 3, h = z & 7;
    const int x0 = blockIdx.x * 32, y0 = blockIdx.y * 8;
    const int t = threadIdx.x;

    for (int i = t; i < 16 * 9; i += 256)
        w_s[i] = dww[(256 + h * 16) * 9 + i];

    const float* src = g_qkv + ((size_t)b * 384 + 256 + h * 16) * L;
    for (int idx = t; idx < 16 * 340; idx += 256) {
        int lc = idx / 340, rem = idx % 340;
        int r = rem / 34, cc = rem % 34;
        int y = y0 + r - 1, x = x0 + cc - 1;
        float v = 0.f;
        if ((unsigned)y < IMG && (unsigned)x < IMG)
            v = src[(size_t)lc * L + y * IMG + x];
        s_in[idx] = v;
    }
    __syncthreads();

    const int tx = t & 31, ty = t >> 5;
    const int p = (y0 + ty) * IMG + x0 + tx;
    float* dst = g_v + ((size_t)b * DIMC + h * 16) * L;
#pragma unroll
    for (int lc = 0; lc < 16; lc++) {
        const float* base = &s_in[lc * 340 + ty * 34 + tx];
        const float* w = &w_s[lc * 9];
        float acc = 0.f;
#pragma unroll
        for (int dy = 0; dy < 3; dy++)
#pragma unroll
            for (int dx = 0; dx < 3; dx++)
                acc += w[dy * 3 + dx] * base[dy * 34 + dx];
        dst[(size_t)lc * L + p] = acc;
    }
}

// ------------------------------------------------------------------
__global__ void attn_small(const float* __restrict__ attca_w,
                           const float* __restrict__ proj_w,
                           const float* __restrict__ temperature)
{
    __shared__ float attnF[BATCH * HEADS * CH][CH];
    const int t = threadIdx.x;
    {
        int bh = t >> 4;
        int c  = t & 15;
        int h  = bh & 7;
        float dq = fmaxf(sqrtf(g_nq[bh * 16 + c]), 1e-12f);
        float temp = temperature[h];
        float row[16];
#pragma unroll
        for (int d = 0; d < 16; d++) {
            float dk = fmaxf(sqrtf(g_nk[bh * 16 + d]), 1e-12f);
            row[d] = g_S[(bh * 16 + c) * 16 + d] / (dq * dk) * temp;
        }
        float m = row[0];
#pragma unroll
        for (int d = 1; d < 16; d++) m = fmaxf(m, row[d]);
        float ex[16], sum = 0.f;
#pragma unroll
        for (int d = 0; d < 16; d++) { ex[d] = expf(row[d] - m); sum += ex[d]; }
        float inv = 1.f / sum;
        float a1[16];
#pragma unroll
        for (int d = 0; d < 16; d++) {
            float r = fmaxf(row[d], 0.f);
            float a = r * r;
            float g = a * 0.5f * (1.f + erff(a * 0.7071067811865476f));
            a1[d] = g * a;
        }
#pragma unroll
        for (int d = 0; d < 16; d++) {
            float sc = 0.f, sh = 0.f;
#pragma unroll
            for (int e = 0; e < 16; e++) {
                sc += attca_w[d * 16 + e] * a1[e];
                sh += attca_w[(16 + d) * 16 + e] * a1[e];
            }
            attnF[bh * 16 + c][d] = ex[d] * inv * (1.f + sc) + sh;
        }
    }
    __syncthreads();
    for (int i = 0; i < 128; i++) {
        int e  = t + (i << 8);
        int b2 = e >> 14;
        int o  = (e >> 7) & 127;
        int j  = e & 127;
        int h2 = j >> 4, d = j & 15;
        float s = 0.f;
#pragma unroll
        for (int c2 = 0; c2 < 16; c2++)
            s += proj_w[o * 128 + h2 * 16 + c2] * attnF[(b2 * 8 + h2) * 16 + c2][d];
        g_M[e] = s;
    }
}

// ------------------------------------------------------------------
extern "C" void kernel_launch(void* const* d_in, const int* in_sizes, int n_in,
                              void* d_out, int out_size)
{
    const float* x           = (const float*)d_in[0];
    const float* qkv_w       = (const float*)d_in[1];
    const float* dw_w        = (const float*)d_in[2];
    const float* proj_w      = (const float*)d_in[3];
    const float* attca_w     = (const float*)d_in[4];
    const float* temperature = (const float*)d_in[5];
    float* out = (float*)d_out;

    float *p_qkv, *p_v, *p_M;
    cudaGetSymbolAddress((void**)&p_qkv, g_qkv);
    cudaGetSymbolAddress((void**)&p_v,   g_v);
    cudaGetSymbolAddress((void**)&p_M,   g_M);

    cudaFuncSetAttribute(tc_gemm, cudaFuncAttributeMaxDynamicSharedMemorySize,
                         SM_BYTES);

    zero_acc<<<16, 256>>>();
    // qkv pointwise: [384x128] @ x[b][128][L]  (weights shared across batch)
    tc_gemm<<<dim3(L / 128, 3, BATCH), 256, SM_BYTES>>>(
        qkv_w, 0, x, (size_t)DIMC * L, p_qkv, (size_t)384 * L);
    // depthwise q/k + Gram reductions
    dw_qk_gram<<<dim3(IMG / 32, IMG / 8, BATCH * HEADS), 256>>>(dw_w);
    // depthwise v
    dw_v<<<dim3(IMG / 32, IMG / 8, BATCH * HEADS), 256>>>(dw_w);
    // attention + fold proj into M
    attn_small<<<1, 256>>>(attca_w, proj_w, temperature);
    // out = M_b @ v
    tc_gemm<<<dim3(L / 128, 1, BATCH), 256, SM_BYTES>>>(
        p_M, (size_t)DIMC * DIMC, p_v, (size_t)DIMC * L, out, (size_t)DIMC * L);
}